// round 4
// baseline (speedup 1.0000x reference)
#include <cuda_runtime.h>
#include <math.h>
#include <stdint.h>

#define B_    8
#define HW_   4096
#define K_    256
#define HID_  1024
#define AUX_  512
#define QK_   512
#define NH_   8
#define HD_   128
#define SCALE_ 0.08838834764831845f   // 1/sqrt(128)

// ---------------- scratch (static device global; no runtime allocs) ----------
__device__ float g_scratch[147324928];

// ---------------- helpers -----------------------------------------------------
__device__ __forceinline__ uint32_t f2tf32(float f) {
    uint32_t u;
    asm("cvt.rna.tf32.f32 %0, %1;" : "=r"(u) : "f"(f));
    return u;
}
__device__ __forceinline__ float roundtf(float f) {
    return __uint_as_float(f2tf32(f));
}
template<bool CVT>
__device__ __forceinline__ uint32_t ldc(float v) {
    return CVT ? f2tf32(v) : __float_as_uint(v);
}

__device__ __forceinline__ void mma8(float* c, const uint32_t* a, const uint32_t* b) {
    asm volatile(
        "mma.sync.aligned.m16n8k8.row.col.f32.tf32.tf32.f32 "
        "{%0,%1,%2,%3}, {%4,%5,%6,%7}, {%8,%9}, {%0,%1,%2,%3};"
        : "+f"(c[0]), "+f"(c[1]), "+f"(c[2]), "+f"(c[3])
        : "r"(a[0]), "r"(a[1]), "r"(a[2]), "r"(a[3]), "r"(b[0]), "r"(b[1]));
}

__device__ __forceinline__ void cp16(void* s, const void* g) {
    uint32_t sa = (uint32_t)__cvta_generic_to_shared(s);
    asm volatile("cp.async.cg.shared.global [%0], [%1], 16;" :: "r"(sa), "l"(g));
}

// ---------------- elementwise tf32 rounding pre-pass -------------------------
__global__ __launch_bounds__(256) void round_kernel(const float* __restrict__ x,
                                                    float* __restrict__ y)
{
    const int i = blockIdx.x * 256 + threadIdx.x;
    float4 v = reinterpret_cast<const float4*>(x)[i];
    v.x = roundtf(v.x); v.y = roundtf(v.y);
    v.z = roundtf(v.z); v.w = roundtf(v.w);
    reinterpret_cast<float4*>(y)[i] = v;
}

// ---------------- tf32 tensor-core batched GEMM ------------------------------
// C[M,N] = alpha * A[M,Kd] * op(B) + bias ; TRANSB: B is [N,Kd], else [Kd,N].
// Block tile 128x128, BK=16, 3-stage cp.async pipeline, 8 warps 64x32 each.
// CVTA/CVTB: convert operand to tf32 at fragment load (false => pre-rounded).
// All outputs stored fp32 (no epilogue rounding).
template<bool TRANSB, bool CVTA, bool CVTB>
__global__ __launch_bounds__(256) void mma_gemm(
    const float* __restrict__ A, const float* __restrict__ Bm,
    const float* __restrict__ bias, float* __restrict__ C,
    int M, int N, int Kd, int lda, int ldb, int ldc_,
    long long sAb, long long sAh, long long sBb, long long sBh,
    long long sCb, long long sCh, int nh, float alpha)
{
    constexpr int LDA_S  = 20;
    constexpr int ASTG   = 128 * LDA_S;
    constexpr int BSTG   = TRANSB ? 128 * LDA_S : 16 * 136;
    extern __shared__ float sm[];
    float* AsB = sm;
    float* BsB = sm + 3 * ASTG;

    const int z  = blockIdx.z;
    const int bb = z / nh, hh = z - bb * nh;
    A  += bb * sAb + hh * sAh;
    Bm += bb * sBb + hh * sBh;
    C  += bb * sCb + hh * sCh;

    const int m0   = blockIdx.y * 128;
    const int n0   = blockIdx.x * 128;
    const int t    = threadIdx.x;
    const int lane = t & 31;
    const int warp = t >> 5;
    const int wm   = (warp >> 2) * 64;
    const int wn   = (warp & 3) * 32;
    const int gid  = lane >> 2;
    const int tig  = lane & 3;

    float acc[4][4][4];
#pragma unroll
    for (int i = 0; i < 4; i++)
#pragma unroll
        for (int j = 0; j < 4; j++)
#pragma unroll
            for (int r = 0; r < 4; r++) acc[i][j][r] = 0.f;

    auto loadA = [&](int s, int k0) {
        float* As = AsB + s * ASTG;
#pragma unroll
        for (int i = 0; i < 2; i++) {
            int c   = t + i * 256;
            int row = c >> 2;
            int off = (c & 3) * 4;
            cp16(&As[row * LDA_S + off], A + (size_t)(m0 + row) * lda + k0 + off);
        }
    };
    auto loadB = [&](int s, int k0) {
        float* Bs = BsB + s * BSTG;
        if (TRANSB) {
#pragma unroll
            for (int i = 0; i < 2; i++) {
                int c   = t + i * 256;
                int row = c >> 2;
                int off = (c & 3) * 4;
                cp16(&Bs[row * LDA_S + off], Bm + (size_t)(n0 + row) * ldb + k0 + off);
            }
        } else {
#pragma unroll
            for (int i = 0; i < 2; i++) {
                int c   = t + i * 256;
                int row = c >> 5;
                int off = (c & 31) * 4;
                cp16(&Bs[row * 136 + off], Bm + (size_t)(k0 + row) * ldb + n0 + off);
            }
        }
    };

    const int nchunk = Kd >> 4;
    loadA(0, 0); loadB(0, 0);
    asm volatile("cp.async.commit_group;");
    if (nchunk > 1) { loadA(1, 16); loadB(1, 16); }
    asm volatile("cp.async.commit_group;");

    for (int ck = 0; ck < nchunk; ck++) {
        asm volatile("cp.async.wait_group 1;");
        __syncthreads();
        if (ck + 2 < nchunk) {
            const int s2 = (ck + 2) % 3;
            loadA(s2, (ck + 2) << 4);
            loadB(s2, (ck + 2) << 4);
        }
        asm volatile("cp.async.commit_group;");

        const int s = ck % 3;
        const float* As = AsB + s * ASTG;
        const float* Bs = BsB + s * BSTG;
#pragma unroll
        for (int k8 = 0; k8 < 16; k8 += 8) {
            uint32_t af[4][4], bf[4][2];
            const int kk = k8 + tig;
#pragma unroll
            for (int mt = 0; mt < 4; mt++) {
                const int r = wm + mt * 16 + gid;
                af[mt][0] = ldc<CVTA>(As[r * LDA_S + kk]);
                af[mt][1] = ldc<CVTA>(As[(r + 8) * LDA_S + kk]);
                af[mt][2] = ldc<CVTA>(As[r * LDA_S + kk + 4]);
                af[mt][3] = ldc<CVTA>(As[(r + 8) * LDA_S + kk + 4]);
            }
#pragma unroll
            for (int nt = 0; nt < 4; nt++) {
                const int col = wn + nt * 8 + gid;
                if (TRANSB) {
                    bf[nt][0] = ldc<CVTB>(Bs[col * LDA_S + kk]);
                    bf[nt][1] = ldc<CVTB>(Bs[col * LDA_S + kk + 4]);
                } else {
                    bf[nt][0] = ldc<CVTB>(Bs[kk * 136 + col]);
                    bf[nt][1] = ldc<CVTB>(Bs[(kk + 4) * 136 + col]);
                }
            }
#pragma unroll
            for (int mt = 0; mt < 4; mt++)
#pragma unroll
                for (int nt = 0; nt < 4; nt++)
                    mma8(acc[mt][nt], af[mt], bf[nt]);
        }
        __syncthreads();
    }

#pragma unroll
    for (int mt = 0; mt < 4; mt++) {
        const int row = m0 + wm + mt * 16 + gid;
#pragma unroll
        for (int nt = 0; nt < 4; nt++) {
            const int col = n0 + wn + nt * 8 + tig * 2;
            float b0v = 0.f, b1v = 0.f;
            if (bias) { b0v = bias[col]; b1v = bias[col + 1]; }
#pragma unroll
            for (int half = 0; half < 2; half++) {
                float2 v;
                v.x = acc[mt][nt][half * 2 + 0] * alpha + b0v;
                v.y = acc[mt][nt][half * 2 + 1] * alpha + b1v;
                *reinterpret_cast<float2*>(C + (size_t)(row + half * 8) * ldc_ + col) = v;
            }
        }
    }
}

// ---------------- softmax, L = 4096, one block per row ----------------------
__global__ __launch_bounds__(256) void softmax4096_kernel(float* __restrict__ X)
{
    float* x = X + (size_t)blockIdx.x * 4096;
    const int t = threadIdx.x;
    float v[16];
    float m = -1e30f;
#pragma unroll
    for (int i = 0; i < 16; i++) { v[i] = x[t + i * 256]; m = fmaxf(m, v[i]); }
    __shared__ float red[8];
    const int lane = t & 31, w = t >> 5;
#pragma unroll
    for (int o = 16; o > 0; o >>= 1) m = fmaxf(m, __shfl_xor_sync(0xffffffffu, m, o));
    if (lane == 0) red[w] = m;
    __syncthreads();
    float bm = red[0];
#pragma unroll
    for (int i = 1; i < 8; i++) bm = fmaxf(bm, red[i]);
    float s = 0.f;
#pragma unroll
    for (int i = 0; i < 16; i++) { v[i] = __expf(v[i] - bm); s += v[i]; }
#pragma unroll
    for (int o = 16; o > 0; o >>= 1) s += __shfl_xor_sync(0xffffffffu, s, o);
    __syncthreads();
    if (lane == 0) red[w] = s;
    __syncthreads();
    float bs = 0.f;
#pragma unroll
    for (int i = 0; i < 8; i++) bs += red[i];
    const float inv = 1.0f / bs;
#pragma unroll
    for (int i = 0; i < 16; i++) x[t + i * 256] = v[i] * inv;
}

// ---------------- softmax, L = 256, one warp per row ------------------------
__global__ __launch_bounds__(256) void softmax256_kernel(float* __restrict__ X)
{
    const int lane = threadIdx.x & 31;
    const int w    = threadIdx.x >> 5;
    float* x = X + ((size_t)blockIdx.x * 8 + w) * 256;
    float v[8];
    float m = -1e30f;
#pragma unroll
    for (int i = 0; i < 8; i++) { v[i] = x[lane + i * 32]; m = fmaxf(m, v[i]); }
#pragma unroll
    for (int o = 16; o > 0; o >>= 1) m = fmaxf(m, __shfl_xor_sync(0xffffffffu, m, o));
    float s = 0.f;
#pragma unroll
    for (int i = 0; i < 8; i++) { v[i] = __expf(v[i] - m); s += v[i]; }
#pragma unroll
    for (int o = 16; o > 0; o >>= 1) s += __shfl_xor_sync(0xffffffffu, s, o);
    const float inv = 1.0f / s;
#pragma unroll
    for (int i = 0; i < 8; i++) x[lane + i * 32] = v[i] * inv;
}

// ---------------- residual add + LayerNorm ----------------------------------
template<int VPT>
__global__ __launch_bounds__(256) void add_ln_kernel(
    const float* __restrict__ R, const float* __restrict__ X,
    const float* __restrict__ g, const float* __restrict__ bta,
    float* __restrict__ Y, int D)
{
    const size_t row = blockIdx.x;
    const float* r = R + row * D;
    const float* x = X + row * D;
    float* y = Y + row * D;
    const int t = threadIdx.x;
    float v[VPT];
    float s = 0.f, sq = 0.f;
#pragma unroll
    for (int i = 0; i < VPT; i++) {
        const int c = t + i * 256;
        v[i] = r[c] + x[c];
        s += v[i]; sq += v[i] * v[i];
    }
    const int lane = t & 31, w = t >> 5;
#pragma unroll
    for (int o = 16; o > 0; o >>= 1) {
        s  += __shfl_xor_sync(0xffffffffu, s, o);
        sq += __shfl_xor_sync(0xffffffffu, sq, o);
    }
    __shared__ float rs[8], rq[8];
    if (lane == 0) { rs[w] = s; rq[w] = sq; }
    __syncthreads();
    s = 0.f; sq = 0.f;
#pragma unroll
    for (int i = 0; i < 8; i++) { s += rs[i]; sq += rq[i]; }
    const float mean = s / D;
    const float var  = sq / D - mean * mean;
    const float inv  = rsqrtf(var + 1e-5f);
#pragma unroll
    for (int i = 0; i < VPT; i++) {
        const int c = t + i * 256;
        y[c] = (v[i] - mean) * inv * g[c] + bta[c];
    }
}

// ---------------- launch ------------------------------------------------------
extern "C" void kernel_launch(void* const* d_in, const int* in_sizes, int n_in,
                              void* d_out, int out_size)
{
    const float* hidden = (const float*)d_in[0];
    const float* aux    = (const float*)d_in[1];
    const float* wq1 = (const float*)d_in[2];  const float* bq1 = (const float*)d_in[3];
    const float* wk1 = (const float*)d_in[4];  const float* bk1 = (const float*)d_in[5];
    const float* wv1 = (const float*)d_in[6];  const float* bv1 = (const float*)d_in[7];
    const float* wo1 = (const float*)d_in[8];  const float* bo1 = (const float*)d_in[9];
    const float* wq2 = (const float*)d_in[10]; const float* bq2 = (const float*)d_in[11];
    const float* wk2 = (const float*)d_in[12]; const float* bk2 = (const float*)d_in[13];
    const float* wv2 = (const float*)d_in[14]; const float* bv2 = (const float*)d_in[15];
    const float* wo2 = (const float*)d_in[16]; const float* bo2 = (const float*)d_in[17];
    const float* g_aux = (const float*)d_in[18]; const float* b_aux = (const float*)d_in[19];
    const float* g_h   = (const float*)d_in[20]; const float* b_h   = (const float*)d_in[21];

    const int SM_T  = 3 * (2560 + 2560) * 4;   // TRANSB variant
    const int SM_NN = 3 * (2560 + 2176) * 4;   // NN variant
    cudaFuncSetAttribute(mma_gemm<true,  false, false>,
        cudaFuncAttributeMaxDynamicSharedMemorySize, SM_T);
    cudaFuncSetAttribute(mma_gemm<true,  true,  true>,
        cudaFuncAttributeMaxDynamicSharedMemorySize, SM_T);
    cudaFuncSetAttribute(mma_gemm<true,  true,  false>,
        cudaFuncAttributeMaxDynamicSharedMemorySize, SM_T);
    cudaFuncSetAttribute(mma_gemm<false, true,  true>,
        cudaFuncAttributeMaxDynamicSharedMemorySize, SM_NN);

    float* scratch = nullptr;
    cudaGetSymbolAddress((void**)&scratch, g_scratch);
    float* q1    = scratch + 0;
    float* k1    = scratch + 1048576;
    float* v1    = scratch + 17825792;
    float* q2    = scratch + 51380224;
    float* k2    = scratch + 68157440;
    float* v2    = scratch + 69206016;
    float* ao1   = scratch + 71303168;
    float* out1  = scratch + 73400320;
    float* ao2   = scratch + 74448896;
    float* out2p = v1;  // v1 dead after attn1@v1
    float* h_r   = scratch + 108003328;
    float* a_r   = scratch + 141557760;
    float* w_r   = scratch + 142606336;
    float* wq1r = w_r;                 // 512*512
    float* wk1r = wq1r + 262144;       // 512*1024
    float* wv1r = wk1r + 524288;       // 1024*1024
    float* wo1r = wv1r + 1048576;      // 512*1024
    float* wq2r = wo1r + 524288;       // 512*1024
    float* wk2r = wq2r + 524288;       // 512*512
    float* wv2r = wk2r + 262144;       // 1024*512
    float* wo2r = wv2r + 524288;       // 1024*1024

    float* out     = (float*)d_out;
    float* aux_out = out + (size_t)B_ * HW_ * HID_;
    float* attn2   = aux_out + (size_t)B_ * K_ * AUX_;
    float* attn1   = attn2 + (size_t)B_ * NH_ * HW_ * K_;

    // --- pre-round pure inputs (provably ≡ cvt-at-load: one rna rounding each)
    round_kernel<<<32768, 256>>>(hidden, h_r);
    round_kernel<<<1024,  256>>>(aux,    a_r);
    round_kernel<<<256,   256>>>(wq1, wq1r);
    round_kernel<<<512,   256>>>(wk1, wk1r);
    round_kernel<<<1024,  256>>>(wv1, wv1r);
    round_kernel<<<512,   256>>>(wo1, wo1r);
    round_kernel<<<512,   256>>>(wq2, wq2r);
    round_kernel<<<256,   256>>>(wk2, wk2r);
    round_kernel<<<512,   256>>>(wv2, wv2r);
    round_kernel<<<1024,  256>>>(wo2, wo2r);

    // --- projections (both operands pre-rounded; outputs fp32) ---
    mma_gemm<true,false,false><<<dim3(4, 16, 1), 256, SM_T>>>(a_r, wq1r, bq1, q1,
        2048, 512, 512, 512, 512, 512, 0, 0, 0, 0, 0, 0, 1, 1.f);
    mma_gemm<true,false,false><<<dim3(4, 256, 1), 256, SM_T>>>(h_r, wk1r, bk1, k1,
        32768, 512, 1024, 1024, 1024, 512, 0, 0, 0, 0, 0, 0, 1, 1.f);
    mma_gemm<true,false,false><<<dim3(8, 256, 1), 256, SM_T>>>(h_r, wv1r, bv1, v1,
        32768, 1024, 1024, 1024, 1024, 1024, 0, 0, 0, 0, 0, 0, 1, 1.f);
    mma_gemm<true,false,false><<<dim3(4, 256, 1), 256, SM_T>>>(h_r, wq2r, bq2, q2,
        32768, 512, 1024, 1024, 1024, 512, 0, 0, 0, 0, 0, 0, 1, 1.f);

    // --- pack attention (GEMM outputs are fp32 -> cvt at load) ---
    mma_gemm<true,true,true><<<dim3(32, 2, 64), 256, SM_T>>>(q1, k1, nullptr, attn1,
        256, 4096, 64, 512, 512, 4096,
        (long long)K_ * QK_, 64,
        (long long)HW_ * QK_, 64,
        (long long)NH_ * K_ * HW_, (long long)K_ * HW_, NH_, SCALE_);
    softmax4096_kernel<<<16384, 256>>>(attn1);
    mma_gemm<false,true,true><<<dim3(1, 2, 64), 256, SM_NN>>>(attn1, v1, nullptr, ao1,
        256, 128, 4096, 4096, 1024, 1024,
        (long long)NH_ * K_ * HW_, (long long)K_ * HW_,
        (long long)HW_ * HID_, HD_,
        (long long)K_ * HID_, HD_, NH_, 1.f);
    mma_gemm<true,true,false><<<dim3(4, 16, 1), 256, SM_T>>>(ao1, wo1r, bo1, out1,
        2048, 512, 1024, 1024, 1024, 512, 0, 0, 0, 0, 0, 0, 1, 1.f);
    add_ln_kernel<2><<<2048, 256>>>(aux, out1, g_aux, b_aux, aux_out, 512);

    // --- unpack attention ---
    mma_gemm<true,true,false><<<dim3(4, 16, 1), 256, SM_T>>>(out1, wk2r, bk2, k2,
        2048, 512, 512, 512, 512, 512, 0, 0, 0, 0, 0, 0, 1, 1.f);
    mma_gemm<true,true,false><<<dim3(8, 16, 1), 256, SM_T>>>(out1, wv2r, bv2, v2,
        2048, 1024, 512, 512, 512, 1024, 0, 0, 0, 0, 0, 0, 1, 1.f);
    mma_gemm<true,true,true><<<dim3(2, 32, 64), 256, SM_T>>>(q2, k2, nullptr, attn2,
        4096, 256, 64, 512, 512, 256,
        (long long)HW_ * QK_, 64,
        (long long)K_ * QK_, 64,
        (long long)NH_ * HW_ * K_, (long long)HW_ * K_, NH_, SCALE_);
    softmax256_kernel<<<32768, 256>>>(attn2);
    mma_gemm<false,true,true><<<dim3(1, 32, 64), 256, SM_NN>>>(attn2, v2, nullptr, ao2,
        4096, 128, 256, 256, 1024, 1024,
        (long long)NH_ * HW_ * K_, (long long)HW_ * K_,
        (long long)K_ * HID_, HD_,
        (long long)HW_ * HID_, HD_, NH_, 1.f);
    mma_gemm<true,true,false><<<dim3(8, 256, 1), 256, SM_T>>>(ao2, wo2r, bo2, out2p,
        32768, 1024, 1024, 1024, 1024, 1024, 0, 0, 0, 0, 0, 0, 1, 1.f);
    add_ln_kernel<4><<<32768, 256>>>(hidden, out2p, g_h, b_h, out, 1024);
}